// round 16
// baseline (speedup 1.0000x reference)
#include <cuda_runtime.h>
#include <cuda_bf16.h>
#include <cstdint>

#define DDIM    512
#define MPTS    131072
#define BQ      64
#define GRID    148
#define NTH     512

#define TILE_M   256
#define NTILES   (MPTS / TILE_M)    // 512
#define NSTEPS   32                 // k16 steps per tile (512/16)

#define VSTRIDE 520                 // bf16 per n-row (bank-safe, proven)
#define VBYTES  (BQ * VSTRIDE * 2)  // 66560

#define PITCH   260                 // ints per k-row in slab (bank-bijective)
#define SLABI   (16 * PITCH)        // 4160 ints per slab
#define SLABB   (SLABI * 4)         // 16640 B
#define NSTAGE  6

#define CTL     (VBYTES + NSTAGE * SLABB)   // 166400
#define S1_OFF   CTL
#define SA_OFF   (CTL + 256)
#define NRM_OFF  (CTL + 512)
#define WS_OFF   (CTL + 576)
#define SMEM_TOTAL (WS_OFF + DDIM * 4)      // ~169 KB

__device__ float g_acc[BQ];
__device__ int   g_arrive = 0;

__device__ __forceinline__ float squashF(float x, float kk, float jj)
{
    float inner = x * (1.f - kk) * __fdividef(1.f, kk * (1.f - 2.f * fabsf(x)) + 1.f);
    float t = 2.f * inner - 1.f;
    return 0.5f + 0.5f * t * (1.f + jj) * __fdividef(1.f, -jj * (1.f - 2.f * fabsf(t)) + 1.f);
}

__device__ __forceinline__ void mma_bf16(float c[4], const uint32_t a[4],
                                         uint32_t b0, uint32_t b1)
{
    asm volatile(
        "mma.sync.aligned.m16n8k16.row.col.f32.bf16.bf16.f32 "
        "{%0,%1,%2,%3}, {%4,%5,%6,%7}, {%8,%9}, {%0,%1,%2,%3};\n"
        : "+f"(c[0]), "+f"(c[1]), "+f"(c[2]), "+f"(c[3])
        : "r"(a[0]), "r"(a[1]), "r"(a[2]), "r"(a[3]), "r"(b0), "r"(b1));
}

__global__ void __launch_bounds__(NTH, 1) knn_main(
    const int*   __restrict__ X1,   // [DDIM][BQ]
    const int*   __restrict__ X2,   // [DDIM][MPTS]
    const float* __restrict__ Y,    // [MPTS]
    const float* __restrict__ W,    // [DDIM]
    const float* __restrict__ alpha,
    const float* __restrict__ beta,
    const float* __restrict__ kp,
    const float* __restrict__ jp,
    float*       __restrict__ out)
{
    extern __shared__ char smem[];
    __nv_bfloat16* V_s = (__nv_bfloat16*)smem;
    int*   slabs = (int*)(smem + VBYTES);
    float* s1_s  = (float*)(smem + S1_OFF);
    float* s_acc = (float*)(smem + SA_OFF);
    float* nrm_s = (float*)(smem + NRM_OFF);
    float* W_s   = (float*)(smem + WS_OFF);
    __shared__ int s_last;

    const int tid  = threadIdx.x;
    const int lane = tid & 31, warp = tid >> 5;
    const int g = lane >> 2, tig = lane & 3;
    const int bid = (int)blockIdx.x;

    const uint32_t slab_u32 = (uint32_t)__cvta_generic_to_shared(slabs);

    const int ntile = (NTILES - bid + GRID - 1) / GRID;
    const int NGC   = ntile * NSTEPS;

    auto issue = [&](int gc) {
        int tile = bid + (gc >> 5) * GRID;
        int d0 = (gc & 31) * 16;
        int base = (gc % NSTAGE) * SLABI;
        const int tm0 = tile << 8;   // tile * 256
        #pragma unroll
        for (int r = 0; r < 2; r++) {
            int id = tid + r * NTH;
            int row = id >> 6, mc = id & 63;
            const int4* src = (const int4*)(X2 + (size_t)(d0 + row) * MPTS + tm0) + mc;
            uint32_t dst = slab_u32 + (uint32_t)((base + row * PITCH) * 4 + mc * 16);
            asm volatile("cp.async.cg.shared.global [%0], [%1], 16;\n" :: "r"(dst), "l"(src));
        }
    };

    // issue first slabs ASAP, overlap DRAM latency with V build
    #pragma unroll
    for (int i = 0; i < NSTAGE - 1; i++) {
        issue(i);
        asm volatile("cp.async.commit_group;\n" ::: "memory");
    }

    // ---------------- prologue: V, s1, norm (proven) ----------------
    W_s[tid] = W[tid];
    if (tid < BQ) { s1_s[tid] = 0.f; s_acc[tid] = 0.f; }
    if (tid == 0) nrm_s[0] = 0.f;
    __syncthreads();
    {
        int b = tid & 63, part = tid >> 6;     // 8 parts of 64 d
        #pragma unroll 4
        for (int d = part; d < DDIM; d += 8) {
            float w = W_s[d];
            int x1 = X1[d * BQ + b];
            V_s[b * VSTRIDE + d] = __float2bfloat16(x1 ? -w : w);
        }
        float s = 0.f;
        #pragma unroll 4
        for (int d = part * 64; d < part * 64 + 64; d++)
            s += W_s[d] * (float)X1[d * BQ + b];
        atomicAdd(&s1_s[b], s);
        float a = fabsf(W_s[tid]);
        #pragma unroll
        for (int o = 16; o; o >>= 1) a += __shfl_down_sync(0xffffffffu, a, o);
        if (lane == 0) atomicAdd(nrm_s, a);
    }
    __syncthreads();

    const float inv_norm = __fdividef(1.f, nrm_s[0] + 1e-6f);
    const float kk = kp[0], jj = jp[0];

    // B ldmatrix lane addressing (proven)
    const int mi = lane >> 3, r8 = lane & 7;
    const int nt_a = mi >> 1, kh = mi & 1;
    const uint32_t v_base = (uint32_t)__cvta_generic_to_shared(V_s);
    uint32_t ldm[4];
    #pragma unroll
    for (int nb = 0; nb < 4; nb++)
        ldm[nb] = v_base + (uint32_t)(((nb * 16 + nt_a * 8 + r8) * VSTRIDE + kh * 8) * 2);

    float sc[16];
    #pragma unroll
    for (int i = 0; i < 16; i++) sc[i] = 0.f;

    float acc[8][4];
    const int lbase = 2 * tig * PITCH + (warp << 4) + g;   // LDS fragment base

    // ---------------- mainloop: slab ring pipeline ----------------
    for (int gc = 0; gc < NGC; gc++) {
        asm volatile("cp.async.wait_group %0;\n" :: "n"(NSTAGE - 2) : "memory");
        __syncthreads();                 // slab[gc] visible to all; slot (gc-1) free
        if (gc + NSTAGE - 1 < NGC) issue(gc + NSTAGE - 1);
        asm volatile("cp.async.commit_group;\n" ::: "memory");

        const int c = gc & 31;
        if (c == 0) {
            #pragma unroll
            for (int nf = 0; nf < 8; nf++)
                #pragma unroll
                for (int i = 0; i < 4; i++) acc[nf][i] = 0.f;
        }

        // fragment reads: 8 conflict-free LDS.32 (pitch 260 -> bank 8*tig+g+d)
        const int* Sl = slabs + (gc % NSTAGE) * SLABI;
        int r0 = Sl[lbase];
        int r1 = Sl[lbase + PITCH];
        int r2 = Sl[lbase + 8];
        int r3 = Sl[lbase + PITCH + 8];
        int r4 = Sl[lbase + 8 * PITCH];
        int r5 = Sl[lbase + 9 * PITCH];
        int r6 = Sl[lbase + 8 * PITCH + 8];
        int r7 = Sl[lbase + 9 * PITCH + 8];

        uint32_t a[4];
        a[0] = (uint32_t)r0 * 0x3F80u + (uint32_t)r1 * 0x3F800000u;
        a[1] = (uint32_t)r2 * 0x3F80u + (uint32_t)r3 * 0x3F800000u;
        a[2] = (uint32_t)r4 * 0x3F80u + (uint32_t)r5 * 0x3F800000u;
        a[3] = (uint32_t)r6 * 0x3F80u + (uint32_t)r7 * 0x3F800000u;

        uint32_t koff = (uint32_t)(c * 32);
        #pragma unroll
        for (int nb = 0; nb < 4; nb++) {
            uint32_t b[4];
            asm volatile(
                "ldmatrix.sync.aligned.m8n8.x4.shared.b16 {%0,%1,%2,%3}, [%4];\n"
                : "=r"(b[0]), "=r"(b[1]), "=r"(b[2]), "=r"(b[3])
                : "r"(ldm[nb] + koff));
            mma_bf16(acc[2 * nb],     a, b[0], b[1]);
            mma_bf16(acc[2 * nb + 1], a, b[2], b[3]);
        }

        if (c == NSTEPS - 1) {
            // ---- fused epilogue for this warp's m16 strip ----
            int tile = bid + (gc >> 5) * GRID;
            int m0 = (tile << 8) + (warp << 4);
            float y0 = __ldg(Y + m0 + g);
            float y1 = __ldg(Y + m0 + 8 + g);
            #pragma unroll
            for (int nf = 0; nf < 8; nf++) {
                int c0 = nf * 8 + 2 * tig;
                float s1a = s1_s[c0], s1b = s1_s[c0 + 1];
                float f00 = squashF(1.f - (s1a + acc[nf][0]) * inv_norm, kk, jj);
                float f01 = squashF(1.f - (s1b + acc[nf][1]) * inv_norm, kk, jj);
                float f10 = squashF(1.f - (s1a + acc[nf][2]) * inv_norm, kk, jj);
                float f11 = squashF(1.f - (s1b + acc[nf][3]) * inv_norm, kk, jj);
                sc[2 * nf]     += f00 * y0 + f10 * y1;
                sc[2 * nf + 1] += f01 * y0 + f11 * y1;
            }
        }
    }

    // ---- reduce sc over the 8 g-lanes sharing each column set ----
    #pragma unroll
    for (int i = 0; i < 16; i++) {
        float v = sc[i];
        v += __shfl_down_sync(0xffffffffu, v, 16);
        v += __shfl_down_sync(0xffffffffu, v, 8);
        v += __shfl_down_sync(0xffffffffu, v, 4);
        if (lane < 4) {
            int col = (i >> 1) * 8 + 2 * lane + (i & 1);
            atomicAdd(&s_acc[col], v);
        }
    }
    __syncthreads();

    // ---------------- light fused finalize (proven R15) ----------------
    if (tid < BQ) atomicAdd(&g_acc[tid], s_acc[tid]);
    __threadfence();
    __syncthreads();
    if (tid == 0) {
        int v = atomicAdd(&g_arrive, 1);
        s_last = (v == GRID - 1);
    }
    __syncthreads();
    if (s_last) {
        if (tid < BQ) {
            float t = g_acc[tid];
            out[tid] = beta[0] * (t * (1.0f / (float)MPTS) + alpha[0]);
            g_acc[tid] = 0.f;          // reset for graph replay
        }
        __syncthreads();
        if (tid == 0) g_arrive = 0;    // reset for graph replay
    }
}

// -------------------- launch --------------------
extern "C" void kernel_launch(void* const* d_in, const int* in_sizes, int n_in,
                              void* d_out, int out_size)
{
    const int*   X1    = (const int*)d_in[0];    // [512,64]
    const int*   X2    = (const int*)d_in[1];    // [512,131072]
    const float* Y     = (const float*)d_in[3];  // [131072]
    const float* W     = (const float*)d_in[4];  // [512]
    const float* alpha = (const float*)d_in[5];
    const float* beta  = (const float*)d_in[6];
    const float* kp    = (const float*)d_in[7];
    const float* jp    = (const float*)d_in[8];
    float* out = (float*)d_out;

    cudaFuncSetAttribute(knn_main, cudaFuncAttributeMaxDynamicSharedMemorySize, SMEM_TOTAL);

    knn_main<<<GRID, NTH, SMEM_TOTAL>>>(X1, X2, Y, W, alpha, beta, kp, jp, out);
}

// round 17
// speedup vs baseline: 1.7820x; 1.7820x over previous
#include <cuda_runtime.h>
#include <cuda_bf16.h>
#include <cstdint>

#define DDIM    512
#define MPTS    131072
#define BQ      64
#define GRID    148
#define NTH     512
#define NWARPS  (GRID * NTH / 32)   // 2368

#define STRIP_M 32
#define NSTRIPS (MPTS / STRIP_M)    // 4096
#define NSTEPS  32                  // k16 steps per strip

#define VSTRIDE 520                 // bf16 per n-row (bank-safe, proven)
#define VBYTES  (BQ * VSTRIDE * 2)  // 66560

#define PITCH   36                  // ints per k-row in per-warp slab (conflict-free)
#define SLAB_I  (16 * PITCH)        // 576 ints = 2304 B per slab
#define NSTAGE  3                   // per-warp slab ring

#define SLABS_B (16 * NSTAGE * SLAB_I * 4)   // 110592
#define CTL     (VBYTES + SLABS_B)           // 177152
#define S1_OFF   CTL
#define SA_OFF   (CTL + 256)
#define NRM_OFF  (CTL + 512)
#define WS_OFF   (CTL + 576)
#define SMEM_TOTAL (WS_OFF + DDIM * 4)       // 179776 (< 227KB)

__device__ float g_acc[BQ];
__device__ int   g_arrive = 0;

__device__ __forceinline__ float squashF(float x, float kk, float jj)
{
    float inner = x * (1.f - kk) * __fdividef(1.f, kk * (1.f - 2.f * fabsf(x)) + 1.f);
    float t = 2.f * inner - 1.f;
    return 0.5f + 0.5f * t * (1.f + jj) * __fdividef(1.f, -jj * (1.f - 2.f * fabsf(t)) + 1.f);
}

__device__ __forceinline__ void mma_bf16(float c[4], const uint32_t a[4],
                                         uint32_t b0, uint32_t b1)
{
    asm volatile(
        "mma.sync.aligned.m16n8k16.row.col.f32.bf16.bf16.f32 "
        "{%0,%1,%2,%3}, {%4,%5,%6,%7}, {%8,%9}, {%0,%1,%2,%3};\n"
        : "+f"(c[0]), "+f"(c[1]), "+f"(c[2]), "+f"(c[3])
        : "r"(a[0]), "r"(a[1]), "r"(a[2]), "r"(a[3]), "r"(b0), "r"(b1));
}

__global__ void __launch_bounds__(NTH, 1) knn_main(
    const int*   __restrict__ X1,   // [DDIM][BQ]
    const int*   __restrict__ X2,   // [DDIM][MPTS]
    const float* __restrict__ Y,    // [MPTS]
    const float* __restrict__ W,    // [DDIM]
    const float* __restrict__ alpha,
    const float* __restrict__ beta,
    const float* __restrict__ kp,
    const float* __restrict__ jp,
    float*       __restrict__ out)
{
    extern __shared__ char smem[];
    __nv_bfloat16* V_s = (__nv_bfloat16*)smem;
    int*   slabs = (int*)(smem + VBYTES);
    float* s1_s  = (float*)(smem + S1_OFF);
    float* s_acc = (float*)(smem + SA_OFF);
    float* nrm_s = (float*)(smem + NRM_OFF);
    float* W_s   = (float*)(smem + WS_OFF);
    __shared__ int s_last;

    const int tid  = threadIdx.x;
    const int lane = tid & 31, warp = tid >> 5;
    const int g = lane >> 2, tig = lane & 3;

    const int gw = (int)blockIdx.x * (NTH / 32) + warp;   // global warp id
    const int nstrips_w = (NSTRIPS - gw + NWARPS - 1) / NWARPS;  // 1 or 2
    const int NGC = nstrips_w * NSTEPS;

    // per-warp slab ring base (ints)
    int* const myslab = slabs + warp * (NSTAGE * SLAB_I);
    const uint32_t myslab_u32 = (uint32_t)__cvta_generic_to_shared(myslab);

    // per-lane cp.async geometry: 4 copies of 16B; copy i covers d-row 4i+(lane>>3)
    const int ld_drow = lane >> 3;          // 0..3
    const int ld_mcol = (lane & 7) * 4;     // 0,4,..,28

    auto issue = [&](int gc) {
        int strip = gw + (gc >> 5) * NWARPS;
        int m0 = strip * STRIP_M;
        int d0 = (gc & 31) * 16;
        uint32_t dbase = myslab_u32 + (uint32_t)(((gc % NSTAGE) * SLAB_I + ld_drow * PITCH + ld_mcol) * 4);
        const int* sbase = X2 + (size_t)(d0 + ld_drow) * MPTS + m0 + ld_mcol;
        #pragma unroll
        for (int i = 0; i < 4; i++) {
            asm volatile("cp.async.cg.shared.global [%0], [%1], 16;\n"
                         :: "r"(dbase + (uint32_t)(4 * i * PITCH * 4)),
                            "l"(sbase + (size_t)(4 * i) * MPTS));
        }
        asm volatile("cp.async.commit_group;\n" ::: "memory");
    };

    // prime the per-warp pipeline before the prologue (overlap DRAM latency)
    issue(0);
    issue(1);

    // ---------------- prologue: V, s1, norm (proven) ----------------
    W_s[tid] = W[tid];
    if (tid < BQ) { s1_s[tid] = 0.f; s_acc[tid] = 0.f; }
    if (tid == 0) nrm_s[0] = 0.f;
    __syncthreads();
    {
        int b = tid & 63, part = tid >> 6;     // 8 parts of 64 d
        #pragma unroll 4
        for (int d = part; d < DDIM; d += 8) {
            float w = W_s[d];
            int x1 = X1[d * BQ + b];
            V_s[b * VSTRIDE + d] = __float2bfloat16(x1 ? -w : w);
        }
        float s = 0.f;
        #pragma unroll 4
        for (int d = part * 64; d < part * 64 + 64; d++)
            s += W_s[d] * (float)X1[d * BQ + b];
        atomicAdd(&s1_s[b], s);
        float a = fabsf(W_s[tid]);
        #pragma unroll
        for (int o = 16; o; o >>= 1) a += __shfl_down_sync(0xffffffffu, a, o);
        if (lane == 0) atomicAdd(nrm_s, a);
    }
    __syncthreads();

    const float inv_norm = __fdividef(1.f, nrm_s[0] + 1e-6f);
    const float kk = kp[0], jj = jp[0];

    // B ldmatrix lane addressing (proven)
    const int mi = lane >> 3, r8 = lane & 7;
    const int nt_a = mi >> 1, kh = mi & 1;
    const uint32_t v_base = (uint32_t)__cvta_generic_to_shared(V_s);
    uint32_t ldm[4];
    #pragma unroll
    for (int nb = 0; nb < 4; nb++)
        ldm[nb] = v_base + (uint32_t)(((nb * 16 + nt_a * 8 + r8) * VSTRIDE + kh * 8) * 2);

    float sc[16];
    #pragma unroll
    for (int i = 0; i < 16; i++) sc[i] = 0.f;

    float acc[2][8][4];
    // LDS fragment base (per m16 tile t at +16t): bank = 8*tig + g + const, conflict-free
    const int lbase = 2 * tig * PITCH + g;

    // ---------------- mainloop: per-warp slab ring, no CTA barriers ----------------
    for (int gc = 0; gc < NGC; gc++) {
        if (gc + 2 < NGC) {
            issue(gc + 2);   // slot (gc+2)%3: not referenced by steps gc, gc+1
            asm volatile("cp.async.wait_group 2;\n" ::: "memory");
        } else {
            asm volatile("cp.async.wait_group 0;\n" ::: "memory");
        }
        __syncwarp();        // cross-lane visibility of slab[gc]

        const int c = gc & 31;
        if (c == 0) {
            #pragma unroll
            for (int t = 0; t < 2; t++)
                #pragma unroll
                for (int nf = 0; nf < 8; nf++)
                    #pragma unroll
                    for (int i = 0; i < 4; i++) acc[t][nf][i] = 0.f;
        }

        const int* Sl = myslab + (gc % NSTAGE) * SLAB_I;
        uint32_t a[2][4];
        #pragma unroll
        for (int t = 0; t < 2; t++) {
            int ib = lbase + 16 * t;
            int x0 = Sl[ib];               // (m=g,   k)
            int x1 = Sl[ib + PITCH];       // (m=g,   k+1)
            int x2 = Sl[ib + 8];           // (m=g+8, k)
            int x3 = Sl[ib + PITCH + 8];   // (m=g+8, k+1)
            int x4 = Sl[ib + 8 * PITCH];         // (m=g,   k+8)
            int x5 = Sl[ib + 9 * PITCH];         // (m=g,   k+9)
            int x6 = Sl[ib + 8 * PITCH + 8];     // (m=g+8, k+8)
            int x7 = Sl[ib + 9 * PITCH + 8];     // (m=g+8, k+9)
            a[t][0] = (uint32_t)x0 * 0x3F80u + (uint32_t)x1 * 0x3F800000u;
            a[t][1] = (uint32_t)x2 * 0x3F80u + (uint32_t)x3 * 0x3F800000u;
            a[t][2] = (uint32_t)x4 * 0x3F80u + (uint32_t)x5 * 0x3F800000u;
            a[t][3] = (uint32_t)x6 * 0x3F80u + (uint32_t)x7 * 0x3F800000u;
        }

        uint32_t koff = (uint32_t)(c * 32);
        #pragma unroll
        for (int nb = 0; nb < 4; nb++) {
            uint32_t b[4];
            asm volatile(
                "ldmatrix.sync.aligned.m8n8.x4.shared.b16 {%0,%1,%2,%3}, [%4];\n"
                : "=r"(b[0]), "=r"(b[1]), "=r"(b[2]), "=r"(b[3])
                : "r"(ldm[nb] + koff));
            #pragma unroll
            for (int t = 0; t < 2; t++) {
                mma_bf16(acc[t][2 * nb],     a[t], b[0], b[1]);
                mma_bf16(acc[t][2 * nb + 1], a[t], b[2], b[3]);
            }
        }

        if (c == NSTEPS - 1) {
            // ---- fused epilogue: two m16 halves of this m32 strip ----
            int strip = gw + (gc >> 5) * NWARPS;
            int m0 = strip * STRIP_M;
            #pragma unroll
            for (int t = 0; t < 2; t++) {
                float y0 = __ldg(Y + m0 + 16 * t + g);
                float y1 = __ldg(Y + m0 + 16 * t + 8 + g);
                #pragma unroll
                for (int nf = 0; nf < 8; nf++) {
                    int c0 = nf * 8 + 2 * tig;
                    float s1a = s1_s[c0], s1b = s1_s[c0 + 1];
                    float f00 = squashF(1.f - (s1a + acc[t][nf][0]) * inv_norm, kk, jj);
                    float f01 = squashF(1.f - (s1b + acc[t][nf][1]) * inv_norm, kk, jj);
                    float f10 = squashF(1.f - (s1a + acc[t][nf][2]) * inv_norm, kk, jj);
                    float f11 = squashF(1.f - (s1b + acc[t][nf][3]) * inv_norm, kk, jj);
                    sc[2 * nf]     += f00 * y0 + f10 * y1;
                    sc[2 * nf + 1] += f01 * y0 + f11 * y1;
                }
            }
        }
    }

    // ---- reduce sc over the 8 g-lanes sharing each column set ----
    #pragma unroll
    for (int i = 0; i < 16; i++) {
        float v = sc[i];
        v += __shfl_down_sync(0xffffffffu, v, 16);
        v += __shfl_down_sync(0xffffffffu, v, 8);
        v += __shfl_down_sync(0xffffffffu, v, 4);
        if (lane < 4) {
            int col = (i >> 1) * 8 + 2 * lane + (i & 1);
            atomicAdd(&s_acc[col], v);
        }
    }
    __syncthreads();

    // ---------------- light fused finalize (proven R15) ----------------
    if (tid < BQ) atomicAdd(&g_acc[tid], s_acc[tid]);
    __threadfence();
    __syncthreads();
    if (tid == 0) {
        int v = atomicAdd(&g_arrive, 1);
        s_last = (v == GRID - 1);
    }
    __syncthreads();
    if (s_last) {
        if (tid < BQ) {
            float t = g_acc[tid];
            out[tid] = beta[0] * (t * (1.0f / (float)MPTS) + alpha[0]);
            g_acc[tid] = 0.f;          // reset for graph replay
        }
        __syncthreads();
        if (tid == 0) g_arrive = 0;    // reset for graph replay
    }
}

// -------------------- launch --------------------
extern "C" void kernel_launch(void* const* d_in, const int* in_sizes, int n_in,
                              void* d_out, int out_size)
{
    const int*   X1    = (const int*)d_in[0];    // [512,64]
    const int*   X2    = (const int*)d_in[1];    // [512,131072]
    const float* Y     = (const float*)d_in[3];  // [131072]
    const float* W     = (const float*)d_in[4];  // [512]
    const float* alpha = (const float*)d_in[5];
    const float* beta  = (const float*)d_in[6];
    const float* kp    = (const float*)d_in[7];
    const float* jp    = (const float*)d_in[8];
    float* out = (float*)d_out;

    cudaFuncSetAttribute(knn_main, cudaFuncAttributeMaxDynamicSharedMemorySize, SMEM_TOTAL);

    knn_main<<<GRID, NTH, SMEM_TOTAL>>>(X1, X2, Y, W, alpha, beta, kp, jp, out);
}